// round 9
// baseline (speedup 1.0000x reference)
#include <cuda_runtime.h>
#include <cuda_fp16.h>

#define CC   128
#define PCH  6
#define SS   131072
#define NTOK 262144
#define TOK  128
#define NTHREADS 256
#define NHEAD 8

#define STRA 68      // fp16 activation row stride (u32 words)
#define ASTR 132     // fp32 residual A column stride: A[c][t], 128 tokens + pad
#define QSTR 65      // Q/K/V fp16 row stride (u32 words)

// ---- shared memory layout (32-bit word offsets) ----
#define OFF_A    0                       // fp32 A [128ch][132tok] col-major = 16896
#define OFF_X    16896                   // fp16 X [128][68]
#define OFF_Q    (OFF_X + TOK*STRA)      // 25600
#define OFF_K    (OFF_Q + TOK*QSTR)      // 33920
#define OFF_V    (OFF_K + TOK*QSTR)      // 42240
#define OFF_X2   OFF_Q                   // relu buffer reuses Q16/K16 (dead in FFN)
#define OFF_POL  (OFF_V + TOK*QSTR)      // 50560
#define SMEM_WORDS (OFF_POL + PCH*TOK)   // 51328
#define SMEM_BYTES (SMEM_WORDS*4)        // 205312 B -> 1 CTA/SM

// 12 fragment blocks of 128x128: Wq,Wk,Wv,Wo, W1 n-chunks x4, W2 k-chunks x4
__device__ unsigned g_wfrag[12 * 8192];

// ---- fp16 helpers ----
__device__ __forceinline__ unsigned pk(float lo, float hi) {
    __half2 h = __floats2half2_rn(lo, hi);
    return *reinterpret_cast<unsigned*>(&h);
}
__device__ __forceinline__ float2 up(unsigned w) {
    __half2 h = *reinterpret_cast<__half2*>(&w);
    return __half22float2(h);
}
__device__ __forceinline__ void mma16(float (&d)[4],
    unsigned a0, unsigned a1, unsigned a2, unsigned a3, unsigned b0, unsigned b1)
{
    asm("mma.sync.aligned.m16n8k16.row.col.f32.f16.f16.f32 "
        "{%0,%1,%2,%3}, {%4,%5,%6,%7}, {%8,%9}, {%0,%1,%2,%3};"
        : "+f"(d[0]), "+f"(d[1]), "+f"(d[2]), "+f"(d[3])
        : "r"(a0), "r"(a1), "r"(a2), "r"(a3), "r"(b0), "r"(b1));
}
__device__ __forceinline__ void ldsm4(unsigned (&a)[4], unsigned addr) {
    asm volatile("ldmatrix.sync.aligned.m8n8.x4.shared.b16 {%0,%1,%2,%3}, [%4];"
        : "=r"(a[0]), "=r"(a[1]), "=r"(a[2]), "=r"(a[3]) : "r"(addr));
}

// ---- weight conversion: fp32 row-major -> fp16 fragment-major (as R6) ----
__global__ void convert_weights(const float* __restrict__ Wq, const float* __restrict__ Wk,
                                const float* __restrict__ Wv, const float* __restrict__ Wo,
                                const float* __restrict__ W1, const float* __restrict__ W2)
{
    int gid = blockIdx.x * blockDim.x + threadIdx.x;
    int blk = gid >> 13;
    int w   = gid & 8191;
    int q4   = w & 3;
    int lane = (w >> 2) & 31;
    int h    = (w >> 7) & 1;
    int nw   = (w >> 8) & 3;
    int ks   = w >> 10;
    int j    = q4 & 1;
    int nt   = h * 2 + (q4 >> 1);
    int qd = lane >> 2, tg = lane & 3;
    int k = ks * 16 + tg * 2 + j * 8;
    int n = nw * 32 + nt * 8 + qd;

    const float* W; int ld = 128, k0 = 0, n0 = 0;
    if      (blk == 0) W = Wq;
    else if (blk == 1) W = Wk;
    else if (blk == 2) W = Wv;
    else if (blk == 3) W = Wo;
    else if (blk < 8)  { W = W1; ld = 512; n0 = (blk - 4) * 128; }
    else               { W = W2; k0 = (blk - 8) * 128; }

    const float* p = W + (size_t)(k0 + k) * ld + n0 + n;
    g_wfrag[gid] = pk(p[0], p[ld]);
}

// ---- A-fragment preload: 16 LDSM -> aH[8 ks][2 mm][4] ----
__device__ __forceinline__ void loadA(unsigned (&aH)[8][2][4],
                                      const unsigned* __restrict__ Xs, int tid)
{
    const int lane = tid & 31, wid = tid >> 5;
    const int mw = wid & 3;
    unsigned abase = (unsigned)__cvta_generic_to_shared(
                        Xs + (mw * 32 + (lane & 15)) * STRA) + ((lane >> 4) << 4);
    #pragma unroll
    for (int ks = 0; ks < 8; ++ks) {
        ldsm4(aH[ks][0], abase + ks * 32);
        ldsm4(aH[ks][1], abase + 16 * STRA * 4 + ks * 32);
    }
}

// ---- GEMM: acc[2 mm][8 nt][4] += A(regs) @ Wfrag, B prefetched 1 ahead ----
// warps: mw = wid&3 (32 rows), nw = wid>>2 (64 cols)
__device__ __forceinline__ void gemmB(
    const unsigned* __restrict__ Wf, const unsigned (&aH)[8][2][4],
    float (&acc)[2][8][4], int tid)
{
    const int lane = tid & 31, wid = tid >> 5;
    const int nw = wid >> 2;
    const uint4* b0 = (const uint4*)Wf + (nw * 2) * 64 + lane;   // ntiles 0-3
    const uint4* b1 = b0 + 64;                                   // ntiles 4-7

    uint4 c00 = b0[0], c01 = b0[32], c10 = b1[0], c11 = b1[32];
    #pragma unroll
    for (int ks = 0; ks < 8; ++ks) {
        uint4 n00 = c00, n01 = c01, n10 = c10, n11 = c11;
        if (ks < 7) {
            n00 = b0[(ks + 1) * 256];      n01 = b0[(ks + 1) * 256 + 32];
            n10 = b1[(ks + 1) * 256];      n11 = b1[(ks + 1) * 256 + 32];
        }
        #pragma unroll
        for (int mm = 0; mm < 2; ++mm) {
            const unsigned a0 = aH[ks][mm][0], a1 = aH[ks][mm][1];
            const unsigned a2 = aH[ks][mm][2], a3 = aH[ks][mm][3];
            mma16(acc[mm][0], a0, a1, a2, a3, c00.x, c00.y);
            mma16(acc[mm][1], a0, a1, a2, a3, c00.z, c00.w);
            mma16(acc[mm][2], a0, a1, a2, a3, c01.x, c01.y);
            mma16(acc[mm][3], a0, a1, a2, a3, c01.z, c01.w);
            mma16(acc[mm][4], a0, a1, a2, a3, c10.x, c10.y);
            mma16(acc[mm][5], a0, a1, a2, a3, c10.z, c10.w);
            mma16(acc[mm][6], a0, a1, a2, a3, c11.x, c11.y);
            mma16(acc[mm][7], a0, a1, a2, a3, c11.z, c11.w);
        }
        c00 = n00; c01 = n01; c10 = n10; c11 = n11;
    }
}

// epilogue -> fp16 buffer stride QSTR (+bias, optional relu)
__device__ __forceinline__ void epi16(float (&acc)[2][8][4], unsigned* __restrict__ dst,
                                      const float* __restrict__ bias, bool relu, int tid)
{
    const int lane = tid & 31, wid = tid >> 5;
    const int mw = wid & 3, nw = wid >> 2;
    const int qd = lane >> 2, tg = lane & 3;
    #pragma unroll
    for (int nt = 0; nt < 8; ++nt) {
        const int cb = nw * 64 + nt * 8 + tg * 2;
        float2 b = *(const float2*)(bias + cb);
        #pragma unroll
        for (int mm = 0; mm < 2; ++mm) {
            const int r0 = mw * 32 + mm * 16 + qd;
            float v0 = acc[mm][nt][0] + b.x, v1 = acc[mm][nt][1] + b.y;
            float v2 = acc[mm][nt][2] + b.x, v3 = acc[mm][nt][3] + b.y;
            if (relu) {
                v0 = fmaxf(v0, 0.f); v1 = fmaxf(v1, 0.f);
                v2 = fmaxf(v2, 0.f); v3 = fmaxf(v3, 0.f);
            }
            dst[r0 * QSTR + (cb >> 1)]       = pk(v0, v1);
            dst[(r0 + 8) * QSTR + (cb >> 1)] = pk(v2, v3);
        }
    }
}

// epilogue -> fp16 buffer stride STRA (relu, for X2)
__device__ __forceinline__ void epi16x(float (&acc)[2][8][4], unsigned* __restrict__ dst,
                                       const float* __restrict__ bias, int tid)
{
    const int lane = tid & 31, wid = tid >> 5;
    const int mw = wid & 3, nw = wid >> 2;
    const int qd = lane >> 2, tg = lane & 3;
    #pragma unroll
    for (int nt = 0; nt < 8; ++nt) {
        const int cb = nw * 64 + nt * 8 + tg * 2;
        float2 b = *(const float2*)(bias + cb);
        #pragma unroll
        for (int mm = 0; mm < 2; ++mm) {
            const int r0 = mw * 32 + mm * 16 + qd;
            float v0 = fmaxf(acc[mm][nt][0] + b.x, 0.f), v1 = fmaxf(acc[mm][nt][1] + b.y, 0.f);
            float v2 = fmaxf(acc[mm][nt][2] + b.x, 0.f), v3 = fmaxf(acc[mm][nt][3] + b.y, 0.f);
            dst[r0 * STRA + (cb >> 1)]       = pk(v0, v1);
            dst[(r0 + 8) * STRA + (cb >> 1)] = pk(v2, v3);
        }
    }
}

// epilogue -> fp32 A (col-major) RMW: A[c][t] += acc (+bias)
__device__ __forceinline__ void epi32A(float (&acc)[2][8][4], float* __restrict__ A,
                                       const float* __restrict__ bias, int tid)
{
    const int lane = tid & 31, wid = tid >> 5;
    const int mw = wid & 3, nw = wid >> 2;
    const int qd = lane >> 2, tg = lane & 3;
    #pragma unroll
    for (int nt = 0; nt < 8; ++nt) {
        const int cb = nw * 64 + nt * 8 + tg * 2;
        float bx = 0.f, by = 0.f;
        if (bias) { float2 b = *(const float2*)(bias + cb); bx = b.x; by = b.y; }
        #pragma unroll
        for (int mm = 0; mm < 2; ++mm) {
            const int r0 = mw * 32 + mm * 16 + qd;
            A[cb * ASTR + r0]           += acc[mm][nt][0] + bx;
            A[(cb + 1) * ASTR + r0]     += acc[mm][nt][1] + by;
            A[cb * ASTR + r0 + 8]       += acc[mm][nt][2] + bx;
            A[(cb + 1) * ASTR + r0 + 8] += acc[mm][nt][3] + by;
        }
    }
}

// LayerNorm: A col-major fp32 -> X row-major fp16. 2 threads/token.
__device__ __forceinline__ void lnA(const float* __restrict__ A, unsigned* __restrict__ X,
                                    const float* __restrict__ g, const float* __restrict__ be, int tid)
{
    const int t = tid >> 1, q = tid & 1;
    const float* Ac = A + q * 64 * ASTR + t;
    float v[64];
    float s = 0.f, sq = 0.f;
    #pragma unroll
    for (int i = 0; i < 64; ++i) {
        v[i] = Ac[i * ASTR];
        s += v[i]; sq += v[i] * v[i];
    }
    s  += __shfl_xor_sync(0xffffffffu, s, 1);
    sq += __shfl_xor_sync(0xffffffffu, sq, 1);
    float m = s * (1.f / CC);
    float rs = rsqrtf(sq * (1.f / CC) - m * m + 1e-5f);

    const float2* g2 = (const float2*)(g + q * 64);
    const float2* b2 = (const float2*)(be + q * 64);
    unsigned* o = X + t * STRA + q * 32;
    #pragma unroll
    for (int i = 0; i < 32; ++i) {
        float2 gg = g2[i], bb = b2[i];
        o[i] = pk((v[2*i] - m) * rs * gg.x + bb.x,
                  (v[2*i+1] - m) * rs * gg.y + bb.y);
    }
}

#define ZACC(a) { _Pragma("unroll") for (int _m = 0; _m < 2; ++_m) _Pragma("unroll") for (int _n = 0; _n < 8; ++_n) { a[_m][_n][0]=0.f; a[_m][_n][1]=0.f; a[_m][_n][2]=0.f; a[_m][_n][3]=0.f; } }

__global__ void __launch_bounds__(NTHREADS, 1)
polar_attention_kernel(
    const float* __restrict__ x,   const float* __restrict__ polar,
    const float* __restrict__ bq,  const float* __restrict__ bk,
    const float* __restrict__ bv,  const float* __restrict__ Wp,
    const float* __restrict__ bpv, const float* __restrict__ bo,
    const float* __restrict__ g1,  const float* __restrict__ be1,
    const float* __restrict__ g2,  const float* __restrict__ be2,
    const float* __restrict__ bf1, const float* __restrict__ bf2,
    float* __restrict__ out)
{
    extern __shared__ float sm[];
    unsigned* smu = (unsigned*)sm;
    float*    A   = sm + OFF_A;
    unsigned* X16 = smu + OFF_X;
    unsigned* Q16 = smu + OFF_Q;
    unsigned* K16 = smu + OFF_K;
    unsigned* V16 = smu + OFF_V;
    unsigned* X2  = smu + OFF_X2;
    float*    pol = sm + OFF_POL;

    const int tid = threadIdx.x;
    const int n0  = blockIdx.x * TOK;
    const int b   = n0 / SS;
    const int s0  = n0 % SS;

    const float* xg = x + (size_t)(b * CC) * SS + s0;
    const float* pg = polar + (size_t)(b * PCH) * SS + s0;

    // ---- load x tile (col-major A) + polar ----
    #pragma unroll
    for (int idx = tid; idx < 4096; idx += NTHREADS) {
        int c = idx >> 5, t4 = (idx & 31) * 4;
        *(float4*)(A + c * ASTR + t4) = *(const float4*)(xg + (size_t)c * SS + t4);
    }
    for (int i = tid; i < PCH * 32; i += NTHREADS) {
        int p = i >> 5, t4 = (i & 31) * 4;
        *(float4*)(pol + p * TOK + t4) = *(const float4*)(pg + (size_t)p * SS + t4);
    }
    __syncthreads();

    // ---- x_with_polar = x + polar @ Wp + bp (A in place) ----
    #pragma unroll
    for (int idx = tid; idx < 4096; idx += NTHREADS) {
        int c = idx >> 5, t4 = (idx & 31) * 4;
        float4 v = *(const float4*)(A + c * ASTR + t4);
        #pragma unroll
        for (int p = 0; p < PCH; ++p) {
            float w = Wp[p * 128 + c];
            float4 pv = *(const float4*)(pol + p * TOK + t4);
            v.x = fmaf(pv.x, w, v.x); v.y = fmaf(pv.y, w, v.y);
            v.z = fmaf(pv.z, w, v.z); v.w = fmaf(pv.w, w, v.w);
        }
        float bb = bpv[c];
        v.x += bb; v.y += bb; v.z += bb; v.w += bb;
        *(float4*)(A + c * ASTR + t4) = v;
    }
    __syncthreads();

    // ---- LN1 -> X16 ----
    lnA(A, X16, g1, be1, tid);
    __syncthreads();

    // ---- Q,K,V: load A-fragments once, reuse across three GEMMs ----
    {
        unsigned aH[8][2][4];
        loadA(aH, X16, tid);
        float acc[2][8][4];
        ZACC(acc); gemmB(g_wfrag,         aH, acc, tid); epi16(acc, Q16, bq, false, tid);
        ZACC(acc); gemmB(g_wfrag + 8192,  aH, acc, tid); epi16(acc, K16, bk, false, tid);
        ZACC(acc); gemmB(g_wfrag + 16384, aH, acc, tid); epi16(acc, V16, bv, false, tid);
    }
    __syncthreads();

    // ---- attention: 2 thr/token, 4 heads each -> X16 ----
    {
        const int t = tid >> 1;
        const int h0q = (tid & 1) * 4;
        const unsigned* Qr = Q16 + t * QSTR;
        const unsigned* Kr = K16 + t * QSTR;
        const unsigned* Vr = V16 + t * QSTR;
        #pragma unroll
        for (int hh = 0; hh < 4; ++hh) {
            const int h = h0q + hh;
            float q[16];
            #pragma unroll
            for (int i = 0; i < 8; ++i) {
                float2 f = up(Qr[h * 8 + i]);
                q[2*i] = f.x; q[2*i+1] = f.y;
            }
            float sc[NHEAD];
            #pragma unroll
            for (int g = 0; g < NHEAD; ++g) {
                float s = 0.f;
                #pragma unroll
                for (int i = 0; i < 8; ++i) {
                    float2 f = up(Kr[g * 8 + i]);
                    s = fmaf(q[2*i], f.x, s);
                    s = fmaf(q[2*i+1], f.y, s);
                }
                sc[g] = s * 0.25f;
            }
            float mx = sc[0];
            #pragma unroll
            for (int g = 1; g < NHEAD; ++g) mx = fmaxf(mx, sc[g]);
            float sum = 0.f;
            #pragma unroll
            for (int g = 0; g < NHEAD; ++g) { float e = __expf(sc[g] - mx); sc[g] = e; sum += e; }
            float inv = 1.f / sum;
            #pragma unroll
            for (int g = 0; g < NHEAD; ++g) sc[g] *= inv;

            float att[16];
            #pragma unroll
            for (int i = 0; i < 16; ++i) att[i] = 0.f;
            #pragma unroll
            for (int g = 0; g < NHEAD; ++g) {
                float w = sc[g];
                #pragma unroll
                for (int i = 0; i < 8; ++i) {
                    float2 f = up(Vr[g * 8 + i]);
                    att[2*i]   = fmaf(w, f.x, att[2*i]);
                    att[2*i+1] = fmaf(w, f.y, att[2*i+1]);
                }
            }
            #pragma unroll
            for (int i = 0; i < 8; ++i)
                X16[t * STRA + h * 8 + i] = pk(att[2*i], att[2*i+1]);
        }
    }
    __syncthreads();

    // ---- out1 = attended @ Wo + bo + residual1 (A RMW) ----
    {
        unsigned aH[8][2][4];
        loadA(aH, X16, tid);
        float acc[2][8][4];
        ZACC(acc); gemmB(g_wfrag + 24576, aH, acc, tid);
        epi32A(acc, A, bo, tid);
    }
    __syncthreads();

    // ---- LN2 -> X16 ----
    lnA(A, X16, g2, be2, tid);
    __syncthreads();

    // ---- FFN: per chunk jb: F1 -> relu X2; F2 partial -> A RMW ----
    #pragma unroll 1
    for (int jb = 0; jb < 4; ++jb) {
        unsigned aH[8][2][4];
        float acc[2][8][4];

        loadA(aH, X16, tid);
        ZACC(acc); gemmB(g_wfrag + (4 + jb) * 8192, aH, acc, tid);
        epi16x(acc, X2, bf1 + jb * 128, tid);       // relu chunk -> X2
        __syncthreads();                            // X2 visible

        loadA(aH, X2, tid);
        __syncthreads();                            // all LDSM of X2 done before next overwrite
        ZACC(acc); gemmB(g_wfrag + (8 + jb) * 8192, aH, acc, tid);
        epi32A(acc, A, jb == 0 ? bf2 : nullptr, tid);
    }
    __syncthreads();

    // ---- coalesced global store ----
    float* og = out + (size_t)(b * CC) * SS + s0;
    #pragma unroll
    for (int idx = tid; idx < 4096; idx += NTHREADS) {
        int c = idx >> 5, t4 = (idx & 31) * 4;
        *(float4*)(og + (size_t)c * SS + t4) = *(const float4*)(A + c * ASTR + t4);
    }
}

extern "C" void kernel_launch(void* const* d_in, const int* in_sizes, int n_in,
                              void* d_out, int out_size)
{
    (void)in_sizes; (void)n_in; (void)out_size;
    cudaFuncSetAttribute(polar_attention_kernel,
                         cudaFuncAttributeMaxDynamicSharedMemorySize, SMEM_BYTES);

    const float* x     = (const float*)d_in[0];
    const float* polar = (const float*)d_in[1];
    const float* Wq    = (const float*)d_in[2];
    const float* bq    = (const float*)d_in[3];
    const float* Wk    = (const float*)d_in[4];
    const float* bk    = (const float*)d_in[5];
    const float* Wv    = (const float*)d_in[6];
    const float* bv    = (const float*)d_in[7];
    const float* Wp    = (const float*)d_in[8];
    const float* bp    = (const float*)d_in[9];
    const float* Wo    = (const float*)d_in[10];
    const float* bo    = (const float*)d_in[11];
    const float* g1    = (const float*)d_in[12];
    const float* be1   = (const float*)d_in[13];
    const float* g2    = (const float*)d_in[14];
    const float* be2   = (const float*)d_in[15];
    const float* W1    = (const float*)d_in[16];
    const float* bf1   = (const float*)d_in[17];
    const float* W2    = (const float*)d_in[18];
    const float* bf2   = (const float*)d_in[19];
    float* out = (float*)d_out;

    convert_weights<<<384, NTHREADS>>>(Wq, Wk, Wv, Wo, W1, W2);

    dim3 grid(NTOK / TOK);   // 2048 CTAs
    polar_attention_kernel<<<grid, NTHREADS, SMEM_BYTES>>>(
        x, polar, bq, bk, bv, Wp, bp, bo, g1, be1, g2, be2, bf1, bf2, out);
}

// round 11
// speedup vs baseline: 1.1099x; 1.1099x over previous
#include <cuda_runtime.h>
#include <cuda_fp16.h>

#define CC   128
#define PCH  6
#define SS   131072
#define NTOK 262144
#define TOK  128
#define NTHREADS 512
#define NHEAD 8

#define ASTR 132     // fp32 residual A column stride: A[c][t]
#define STRA 68      // fp16 LDSM-able activation row stride (u32 words)
#define QSTR 65      // Q/K/V fp16 row stride (u32 words)

// ---- shared memory layout (u32 word offsets) ----
#define OFF_A    0                       // fp32 A [128ch][132tok] col-major = 16896
#define OFF_X    16896                   // fp16 X [128][68] (LDSM)
#define OFF_Q    25600                   // [128][65]
#define OFF_K    33920
#define OFF_V    42240
#define OFF_X2A  OFF_Q                   // FFN relu buf A [128][68] (Q/K dead in FFN)
#define OFF_X2B  (OFF_Q + TOK*STRA)      // 34304, FFN relu buf B (K/V dead in FFN)
#define OFF_POL  50560                   // polar [6][128]
#define SMEM_WORDS 51328
#define SMEM_BYTES (SMEM_WORDS*4)        // 205312 B -> 1 CTA/SM, 512 thr

// 12 fragment blocks of 128x128: Wq,Wk,Wv,Wo, W1 n-chunks x4, W2 k-chunks x4
__device__ unsigned g_wfrag[12 * 8192];

__device__ __forceinline__ unsigned pk(float lo, float hi) {
    __half2 h = __floats2half2_rn(lo, hi);
    return *reinterpret_cast<unsigned*>(&h);
}
__device__ __forceinline__ float2 up(unsigned w) {
    __half2 h = *reinterpret_cast<__half2*>(&w);
    return __half22float2(h);
}
__device__ __forceinline__ void mma16(float (&d)[4],
    unsigned a0, unsigned a1, unsigned a2, unsigned a3, unsigned b0, unsigned b1)
{
    asm("mma.sync.aligned.m16n8k16.row.col.f32.f16.f16.f32 "
        "{%0,%1,%2,%3}, {%4,%5,%6,%7}, {%8,%9}, {%0,%1,%2,%3};"
        : "+f"(d[0]), "+f"(d[1]), "+f"(d[2]), "+f"(d[3])
        : "r"(a0), "r"(a1), "r"(a2), "r"(a3), "r"(b0), "r"(b1));
}
__device__ __forceinline__ void ldsm4(unsigned (&a)[4], unsigned addr) {
    asm volatile("ldmatrix.sync.aligned.m8n8.x4.shared.b16 {%0,%1,%2,%3}, [%4];"
        : "=r"(a[0]), "=r"(a[1]), "=r"(a[2]), "=r"(a[3]) : "r"(addr));
}

// ---- weight conversion: fp32 row-major -> fp16 fragment-major (n32 groups) ----
__global__ void convert_weights(const float* __restrict__ Wq, const float* __restrict__ Wk,
                                const float* __restrict__ Wv, const float* __restrict__ Wo,
                                const float* __restrict__ W1, const float* __restrict__ W2)
{
    int gid = blockIdx.x * blockDim.x + threadIdx.x;
    int blk = gid >> 13;
    int w   = gid & 8191;
    int q4   = w & 3;
    int lane = (w >> 2) & 31;
    int h    = (w >> 7) & 1;
    int nw   = (w >> 8) & 3;
    int ks   = w >> 10;
    int j    = q4 & 1;
    int nt   = h * 2 + (q4 >> 1);
    int qd = lane >> 2, tg = lane & 3;
    int k = ks * 16 + tg * 2 + j * 8;
    int n = nw * 32 + nt * 8 + qd;

    const float* W; int ld = 128, k0 = 0, n0 = 0;
    if      (blk == 0) W = Wq;
    else if (blk == 1) W = Wk;
    else if (blk == 2) W = Wv;
    else if (blk == 3) W = Wo;
    else if (blk < 8)  { W = W1; ld = 512; n0 = (blk - 4) * 128; }
    else               { W = W2; k0 = (blk - 8) * 128; }

    const float* p = W + (size_t)(k0 + k) * ld + n0 + n;
    g_wfrag[gid] = pk(p[0], p[ld]);
}

// ---- GEMM m32n32, 16 warps (4m x 4n): acc[2 mm][4 nt][4]; A+B pipelined ----
__device__ __forceinline__ void gemm32(
    const unsigned* __restrict__ Wf, const unsigned* __restrict__ Xs,
    float (&acc)[2][4][4], int tid)
{
    const int lane = tid & 31, wid = tid >> 5;
    const int mw = wid & 3, nw = wid >> 2;       // mw 0..3, nw 0..3
    unsigned abase = (unsigned)__cvta_generic_to_shared(
                        Xs + (mw * 32 + (lane & 15)) * STRA) + ((lane >> 4) << 4);
    const uint4* b0 = (const uint4*)Wf + nw * 64 + lane;

    unsigned aC[2][4], aN[2][4];
    uint4 c0, c1;
    ldsm4(aC[0], abase);
    ldsm4(aC[1], abase + 16 * STRA * 4);
    c0 = b0[0]; c1 = b0[32];

    #pragma unroll
    for (int ks = 0; ks < 8; ++ks) {
        uint4 n0 = c0, n1 = c1;
        if (ks < 7) {
            unsigned an = abase + (ks + 1) * 32;
            ldsm4(aN[0], an);
            ldsm4(aN[1], an + 16 * STRA * 4);
            n0 = b0[(ks + 1) * 256];
            n1 = b0[(ks + 1) * 256 + 32];
        }
        #pragma unroll
        for (int mm = 0; mm < 2; ++mm) {
            const unsigned a0 = aC[mm][0], a1 = aC[mm][1], a2 = aC[mm][2], a3 = aC[mm][3];
            mma16(acc[mm][0], a0, a1, a2, a3, c0.x, c0.y);
            mma16(acc[mm][1], a0, a1, a2, a3, c0.z, c0.w);
            mma16(acc[mm][2], a0, a1, a2, a3, c1.x, c1.y);
            mma16(acc[mm][3], a0, a1, a2, a3, c1.z, c1.w);
        }
        #pragma unroll
        for (int mm = 0; mm < 2; ++mm)
            #pragma unroll
            for (int r = 0; r < 4; ++r) aC[mm][r] = aN[mm][r];
        c0 = n0; c1 = n1;
    }
}

// epilogue -> fp16 buffer stride QSTR, +bias (QKV)
__device__ __forceinline__ void epi16q(float (&acc)[2][4][4], unsigned* __restrict__ dst,
                                       const float* __restrict__ bias, int tid)
{
    const int lane = tid & 31, wid = tid >> 5;
    const int mw = wid & 3, nw = wid >> 2;
    const int qd = lane >> 2, tg = lane & 3;
    #pragma unroll
    for (int nt = 0; nt < 4; ++nt) {
        const int cb = nw * 32 + nt * 8 + tg * 2;
        float2 b = *(const float2*)(bias + cb);
        #pragma unroll
        for (int mm = 0; mm < 2; ++mm) {
            const int r0 = mw * 32 + mm * 16 + qd;
            dst[r0 * QSTR + (cb >> 1)]       = pk(acc[mm][nt][0] + b.x, acc[mm][nt][1] + b.y);
            dst[(r0 + 8) * QSTR + (cb >> 1)] = pk(acc[mm][nt][2] + b.x, acc[mm][nt][3] + b.y);
        }
    }
}

// epilogue -> fp16 buffer stride STRA, relu (FFN F1)
__device__ __forceinline__ void epi16x(float (&acc)[2][4][4], unsigned* __restrict__ dst,
                                       const float* __restrict__ bias, int tid)
{
    const int lane = tid & 31, wid = tid >> 5;
    const int mw = wid & 3, nw = wid >> 2;
    const int qd = lane >> 2, tg = lane & 3;
    #pragma unroll
    for (int nt = 0; nt < 4; ++nt) {
        const int cb = nw * 32 + nt * 8 + tg * 2;
        float2 b = *(const float2*)(bias + cb);
        #pragma unroll
        for (int mm = 0; mm < 2; ++mm) {
            const int r0 = mw * 32 + mm * 16 + qd;
            dst[r0 * STRA + (cb >> 1)]       = pk(fmaxf(acc[mm][nt][0] + b.x, 0.f),
                                                  fmaxf(acc[mm][nt][1] + b.y, 0.f));
            dst[(r0 + 8) * STRA + (cb >> 1)] = pk(fmaxf(acc[mm][nt][2] + b.x, 0.f),
                                                  fmaxf(acc[mm][nt][3] + b.y, 0.f));
        }
    }
}

// epilogue -> fp32 A (col-major) RMW: A[c][t] += acc + bias
__device__ __forceinline__ void epi32A(float (&acc)[2][4][4], float* __restrict__ A,
                                       const float* __restrict__ bias, int tid)
{
    const int lane = tid & 31, wid = tid >> 5;
    const int mw = wid & 3, nw = wid >> 2;
    const int qd = lane >> 2, tg = lane & 3;
    #pragma unroll
    for (int nt = 0; nt < 4; ++nt) {
        const int cb = nw * 32 + nt * 8 + tg * 2;
        float2 b = *(const float2*)(bias + cb);
        #pragma unroll
        for (int mm = 0; mm < 2; ++mm) {
            const int r0 = mw * 32 + mm * 16 + qd;
            A[cb * ASTR + r0]           += acc[mm][nt][0] + b.x;
            A[(cb + 1) * ASTR + r0]     += acc[mm][nt][1] + b.y;
            A[cb * ASTR + r0 + 8]       += acc[mm][nt][2] + b.x;
            A[(cb + 1) * ASTR + r0 + 8] += acc[mm][nt][3] + b.y;
        }
    }
}

// LayerNorm: A col-major fp32 -> X (LDSM layout) fp16. 4 threads/token.
__device__ __forceinline__ void lnA(const float* __restrict__ A, unsigned* __restrict__ X,
                                    const float* __restrict__ g, const float* __restrict__ be, int tid)
{
    const int t = tid >> 2, q = tid & 3;
    const float* Ac = A + q * 32 * ASTR + t;
    float v[32];
    float s = 0.f, sq = 0.f;
    #pragma unroll
    for (int i = 0; i < 32; ++i) {
        v[i] = Ac[i * ASTR];
        s += v[i]; sq += v[i] * v[i];
    }
    s  += __shfl_xor_sync(0xffffffffu, s, 1);
    sq += __shfl_xor_sync(0xffffffffu, sq, 1);
    s  += __shfl_xor_sync(0xffffffffu, s, 2);
    sq += __shfl_xor_sync(0xffffffffu, sq, 2);
    float m = s * (1.f / CC);
    float rs = rsqrtf(sq * (1.f / CC) - m * m + 1e-5f);

    const float2* g2 = (const float2*)(g + q * 32);
    const float2* b2 = (const float2*)(be + q * 32);
    unsigned* o = X + t * STRA + q * 16;
    #pragma unroll
    for (int i = 0; i < 16; ++i) {
        float2 gg = g2[i], bb = b2[i];
        o[i] = pk((v[2*i] - m) * rs * gg.x + bb.x,
                  (v[2*i+1] - m) * rs * gg.y + bb.y);
    }
}

#define ZACC4(a) { _Pragma("unroll") for (int _m = 0; _m < 2; ++_m) _Pragma("unroll") for (int _n = 0; _n < 4; ++_n) { a[_m][_n][0]=0.f; a[_m][_n][1]=0.f; a[_m][_n][2]=0.f; a[_m][_n][3]=0.f; } }

__global__ void __launch_bounds__(NTHREADS, 1)
polar_attention_kernel(
    const float* __restrict__ x,   const float* __restrict__ polar,
    const float* __restrict__ bq,  const float* __restrict__ bk,
    const float* __restrict__ bv,  const float* __restrict__ Wp,
    const float* __restrict__ bpv, const float* __restrict__ bo,
    const float* __restrict__ g1,  const float* __restrict__ be1,
    const float* __restrict__ g2,  const float* __restrict__ be2,
    const float* __restrict__ bf1, const float* __restrict__ bf2,
    float* __restrict__ out)
{
    extern __shared__ float sm[];
    unsigned* smu = (unsigned*)sm;
    float*    A   = sm + OFF_A;
    unsigned* X16 = smu + OFF_X;
    unsigned* Q16 = smu + OFF_Q;
    unsigned* K16 = smu + OFF_K;
    unsigned* V16 = smu + OFF_V;
    float*    pol = sm + OFF_POL;

    const int tid = threadIdx.x;
    const int n0  = blockIdx.x * TOK;
    const int b   = n0 / SS;
    const int s0  = n0 % SS;

    const float* xg = x + (size_t)(b * CC) * SS + s0;
    const float* pg = polar + (size_t)(b * PCH) * SS + s0;

    // ---- load x tile (col-major A) + polar ----
    #pragma unroll
    for (int idx = tid; idx < 4096; idx += NTHREADS) {
        int c = idx >> 5, t4 = (idx & 31) * 4;
        *(float4*)(A + c * ASTR + t4) = *(const float4*)(xg + (size_t)c * SS + t4);
    }
    for (int i = tid; i < PCH * 32; i += NTHREADS) {
        int p = i >> 5, t4 = (i & 31) * 4;
        *(float4*)(pol + p * TOK + t4) = *(const float4*)(pg + (size_t)p * SS + t4);
    }
    __syncthreads();

    // ---- x_with_polar = x + polar @ Wp + bp (A in place) ----
    #pragma unroll
    for (int idx = tid; idx < 4096; idx += NTHREADS) {
        int c = idx >> 5, t4 = (idx & 31) * 4;
        float4 v = *(const float4*)(A + c * ASTR + t4);
        #pragma unroll
        for (int p = 0; p < PCH; ++p) {
            float w = Wp[p * 128 + c];
            float4 pv = *(const float4*)(pol + p * TOK + t4);
            v.x = fmaf(pv.x, w, v.x); v.y = fmaf(pv.y, w, v.y);
            v.z = fmaf(pv.z, w, v.z); v.w = fmaf(pv.w, w, v.w);
        }
        float bb = bpv[c];
        v.x += bb; v.y += bb; v.z += bb; v.w += bb;
        *(float4*)(A + c * ASTR + t4) = v;
    }
    __syncthreads();

    // ---- LN1 -> X16 ----
    lnA(A, X16, g1, be1, tid);
    __syncthreads();

    // ---- Q,K,V (m32n32, 16 warps) ----
    {
        float acc[2][4][4];
        ZACC4(acc); gemm32(g_wfrag,         X16, acc, tid); epi16q(acc, Q16, bq, tid);
        ZACC4(acc); gemm32(g_wfrag + 8192,  X16, acc, tid); epi16q(acc, K16, bk, tid);
        ZACC4(acc); gemm32(g_wfrag + 16384, X16, acc, tid); epi16q(acc, V16, bv, tid);
    }
    __syncthreads();

    // ---- attention: 4 thr/token, 2 heads each -> X16 ----
    {
        const int t = tid >> 2;
        const int h0q = (tid & 3) * 2;
        const unsigned* Qr = Q16 + t * QSTR;
        const unsigned* Kr = K16 + t * QSTR;
        const unsigned* Vr = V16 + t * QSTR;
        #pragma unroll
        for (int hh = 0; hh < 2; ++hh) {
            const int h = h0q + hh;
            float q[16];
            #pragma unroll
            for (int i = 0; i < 8; ++i) {
                float2 f = up(Qr[h * 8 + i]);
                q[2*i] = f.x; q[2*i+1] = f.y;
            }
            float sc[NHEAD];
            #pragma unroll
            for (int g = 0; g < NHEAD; ++g) {
                float s = 0.f;
                #pragma unroll
                for (int i = 0; i < 8; ++i) {
                    float2 f = up(Kr[g * 8 + i]);
                    s = fmaf(q[2*i], f.x, s);
                    s = fmaf(q[2*i+1], f.y, s);
                }
                sc[g] = s * 0.25f;
            }
            float mx = sc[0];
            #pragma unroll
            for (int g = 1; g < NHEAD; ++g) mx = fmaxf(mx, sc[g]);
            float sum = 0.f;
            #pragma unroll
            for (int g = 0; g < NHEAD; ++g) { float e = __expf(sc[g] - mx); sc[g] = e; sum += e; }
            float inv = 1.f / sum;
            #pragma unroll
            for (int g = 0; g < NHEAD; ++g) sc[g] *= inv;

            float att[16];
            #pragma unroll
            for (int i = 0; i < 16; ++i) att[i] = 0.f;
            #pragma unroll
            for (int g = 0; g < NHEAD; ++g) {
                float w = sc[g];
                #pragma unroll
                for (int i = 0; i < 8; ++i) {
                    float2 f = up(Vr[g * 8 + i]);
                    att[2*i]   = fmaf(w, f.x, att[2*i]);
                    att[2*i+1] = fmaf(w, f.y, att[2*i+1]);
                }
            }
            #pragma unroll
            for (int i = 0; i < 8; ++i)
                X16[t * STRA + h * 8 + i] = pk(att[2*i], att[2*i+1]);
        }
    }
    __syncthreads();

    // ---- out1 = attended @ Wo + bo + residual1 (A RMW) ----
    {
        float acc[2][4][4];
        ZACC4(acc); gemm32(g_wfrag + 24576, X16, acc, tid);
        epi32A(acc, A, bo, tid);
    }
    __syncthreads();

    // ---- LN2 -> X16 ----
    lnA(A, X16, g2, be2, tid);
    __syncthreads();

    // ---- FFN: acc2 held across 4 k-chunks; relu double-buffered ----
    {
        float acc2[2][4][4];
        ZACC4(acc2);
        #pragma unroll 1
        for (int jb = 0; jb < 4; ++jb) {
            unsigned* X2 = smu + ((jb & 1) ? OFF_X2B : OFF_X2A);
            float h1[2][4][4];
            ZACC4(h1);
            gemm32(g_wfrag + (4 + jb) * 8192, X16, h1, tid);
            epi16x(h1, X2, bf1 + jb * 128, tid);
            __syncthreads();                       // X2 visible (buffer alternates;
                                                   // prior buffer's reads done >=1 sync ago)
            gemm32(g_wfrag + (8 + jb) * 8192, X2, acc2, tid);
        }
        __syncthreads();
        epi32A(acc2, A, bf2, tid);
    }
    __syncthreads();

    // ---- coalesced global store ----
    float* og = out + (size_t)(b * CC) * SS + s0;
    #pragma unroll
    for (int idx = tid; idx < 4096; idx += NTHREADS) {
        int c = idx >> 5, t4 = (idx & 31) * 4;
        *(float4*)(og + (size_t)c * SS + t4) = *(const float4*)(A + c * ASTR + t4);
    }
}

extern "C" void kernel_launch(void* const* d_in, const int* in_sizes, int n_in,
                              void* d_out, int out_size)
{
    (void)in_sizes; (void)n_in; (void)out_size;
    cudaFuncSetAttribute(polar_attention_kernel,
                         cudaFuncAttributeMaxDynamicSharedMemorySize, SMEM_BYTES);

    const float* x     = (const float*)d_in[0];
    const float* polar = (const float*)d_in[1];
    const float* Wq    = (const float*)d_in[2];
    const float* bq    = (const float*)d_in[3];
    const float* Wk    = (const float*)d_in[4];
    const float* bk    = (const float*)d_in[5];
    const float* Wv    = (const float*)d_in[6];
    const float* bv    = (const float*)d_in[7];
    const float* Wp    = (const float*)d_in[8];
    const float* bp    = (const float*)d_in[9];
    const float* Wo    = (const float*)d_in[10];
    const float* bo    = (const float*)d_in[11];
    const float* g1    = (const float*)d_in[12];
    const float* be1   = (const float*)d_in[13];
    const float* g2    = (const float*)d_in[14];
    const float* be2   = (const float*)d_in[15];
    const float* W1    = (const float*)d_in[16];
    const float* bf1   = (const float*)d_in[17];
    const float* W2    = (const float*)d_in[18];
    const float* bf2   = (const float*)d_in[19];
    float* out = (float*)d_out;

    convert_weights<<<384, 256>>>(Wq, Wk, Wv, Wo, W1, W2);

    dim3 grid(NTOK / TOK);   // 2048 CTAs
    polar_attention_kernel<<<grid, NTHREADS, SMEM_BYTES>>>(
        x, polar, bq, bk, bv, Wp, bp, bo, g1, be1, g2, be2, bf1, bf2, out);
}

// round 12
// speedup vs baseline: 1.5069x; 1.3576x over previous
#include <cuda_runtime.h>
#include <cuda_fp16.h>

#define CC   128
#define PCH  6
#define SS   131072
#define NTOK 262144
#define TOK  64
#define NTHREADS 256
#define NHEAD 8

#define STRA 68      // fp16 activation row stride (u32 words)
#define ASTR 68      // fp32 residual A column stride: A[c][t]

// ---- shared memory layout (32-bit word offsets) ----
#define OFF_A    0                       // fp32 A [128][68] col-major
#define OFF_X    (128*ASTR)              // 8704
#define OFF_Q    (OFF_X + 64*STRA)       // 13056
#define OFF_K    (OFF_Q + 64*STRA)       // 17408
#define OFF_V    (OFF_K + 64*STRA)       // 21760
#define OFF_X2A  OFF_Q                   // FFN relu buf A (Q dead in FFN)
#define OFF_X2B  OFF_K                   // FFN relu buf B (K dead in FFN)
#define OFF_POL  (OFF_V + 64*STRA)       // 26112
#define OFF_RED  (OFF_POL + PCH*64)      // 26496: LN reduction scratch [2][4][64]
#define SMEM_WORDS (OFF_RED + 512)       // 27008
#define SMEM_BYTES (SMEM_WORDS*4)        // 108032 B -> 2 CTAs/SM

// 12 fragment blocks of 128x128: Wq,Wk,Wv,Wo, W1 n-chunks x4, W2 k-chunks x4
__device__ unsigned g_wfrag[12 * 8192];

// ---- fp16 helpers ----
__device__ __forceinline__ unsigned pk(float lo, float hi) {
    __half2 h = __floats2half2_rn(lo, hi);
    return *reinterpret_cast<unsigned*>(&h);
}
__device__ __forceinline__ float2 up(unsigned w) {
    __half2 h = *reinterpret_cast<__half2*>(&w);
    return __half22float2(h);
}
__device__ __forceinline__ void up8(float* f, uint4 u) {
    float2 a = up(u.x), b = up(u.y), c = up(u.z), d = up(u.w);
    f[0] = a.x; f[1] = a.y; f[2] = b.x; f[3] = b.y;
    f[4] = c.x; f[5] = c.y; f[6] = d.x; f[7] = d.y;
}
__device__ __forceinline__ void mma16(float (&d)[4],
    unsigned a0, unsigned a1, unsigned a2, unsigned a3, unsigned b0, unsigned b1)
{
    asm("mma.sync.aligned.m16n8k16.row.col.f32.f16.f16.f32 "
        "{%0,%1,%2,%3}, {%4,%5,%6,%7}, {%8,%9}, {%0,%1,%2,%3};"
        : "+f"(d[0]), "+f"(d[1]), "+f"(d[2]), "+f"(d[3])
        : "r"(a0), "r"(a1), "r"(a2), "r"(a3), "r"(b0), "r"(b1));
}
__device__ __forceinline__ void ldsm4(unsigned (&a)[4], unsigned addr) {
    asm volatile("ldmatrix.sync.aligned.m8n8.x4.shared.b16 {%0,%1,%2,%3}, [%4];"
        : "=r"(a[0]), "=r"(a[1]), "=r"(a[2]), "=r"(a[3]) : "r"(addr));
}

// ---- weight conversion kernel: fp32 row-major -> fp16 fragment-major ----
__global__ void convert_weights(const float* __restrict__ Wq, const float* __restrict__ Wk,
                                const float* __restrict__ Wv, const float* __restrict__ Wo,
                                const float* __restrict__ W1, const float* __restrict__ W2)
{
    int gid = blockIdx.x * blockDim.x + threadIdx.x;
    int blk = gid >> 13;
    int w   = gid & 8191;
    int q4   = w & 3;
    int lane = (w >> 2) & 31;
    int h    = (w >> 7) & 1;
    int nw   = (w >> 8) & 3;
    int ks   = w >> 10;
    int j    = q4 & 1;
    int nt   = h * 2 + (q4 >> 1);
    int qd = lane >> 2, tg = lane & 3;
    int k = ks * 16 + tg * 2 + j * 8;
    int n = nw * 32 + nt * 8 + qd;

    const float* W; int ld = 128, k0 = 0, n0 = 0;
    if      (blk == 0) W = Wq;
    else if (blk == 1) W = Wk;
    else if (blk == 2) W = Wv;
    else if (blk == 3) W = Wo;
    else if (blk < 8)  { W = W1; ld = 512; n0 = (blk - 4) * 128; }
    else               { W = W2; k0 = (blk - 8) * 128; }

    const float* p = W + (size_t)(k0 + k) * ld + n0 + n;
    g_wfrag[gid] = pk(p[0], p[ld]);
}

// ---- GEMM: acc[2][4][4] += X[64x128 fp16] @ Wfrag, software pipelined ----
// warps: mw = wid&1 (32 rows), nw = wid>>1 (32 cols)
__device__ __forceinline__ void gemm_f(
    const unsigned* __restrict__ Wf,
    const unsigned* __restrict__ Xs,
    float (&acc)[2][4][4], int tid)
{
    const int lane = tid & 31, wid = tid >> 5;
    const int mw = wid & 1, nw = wid >> 1;

    unsigned abase;
    {
        const unsigned* p = Xs + (mw * 32 + (lane & 15)) * STRA;
        abase = (unsigned)__cvta_generic_to_shared(p) + ((lane >> 4) << 4);
    }
    const uint4* bp = (const uint4*)Wf + nw * 64 + lane;

    unsigned aC[2][4], aN[2][4];
    uint4 b0C, b1C, b0N, b1N;
    ldsm4(aC[0], abase);
    ldsm4(aC[1], abase + 16 * STRA * 4);
    b0C = bp[0]; b1C = bp[32];

    #pragma unroll
    for (int ks = 0; ks < 8; ++ks) {
        if (ks < 7) {
            unsigned an = abase + (ks + 1) * 32;
            ldsm4(aN[0], an);
            ldsm4(aN[1], an + 16 * STRA * 4);
            b0N = bp[(ks + 1) * 256];
            b1N = bp[(ks + 1) * 256 + 32];
        }
        #pragma unroll
        for (int mm = 0; mm < 2; ++mm) {
            mma16(acc[mm][0], aC[mm][0], aC[mm][1], aC[mm][2], aC[mm][3], b0C.x, b0C.y);
            mma16(acc[mm][1], aC[mm][0], aC[mm][1], aC[mm][2], aC[mm][3], b0C.z, b0C.w);
            mma16(acc[mm][2], aC[mm][0], aC[mm][1], aC[mm][2], aC[mm][3], b1C.x, b1C.y);
            mma16(acc[mm][3], aC[mm][0], aC[mm][1], aC[mm][2], aC[mm][3], b1C.z, b1C.w);
        }
        #pragma unroll
        for (int mm = 0; mm < 2; ++mm)
            #pragma unroll
            for (int r = 0; r < 4; ++r) aC[mm][r] = aN[mm][r];
        b0C = b0N; b1C = b1N;
    }
}

// epilogue -> fp16 activation buffer (+bias from gmem, optional relu)
__device__ __forceinline__ void epi16(float (&acc)[2][4][4], unsigned* __restrict__ dst,
                                      const float* __restrict__ bias, bool relu, int tid)
{
    const int lane = tid & 31, wid = tid >> 5;
    const int mw = wid & 1, nw = wid >> 1;
    const int qd = lane >> 2, tg = lane & 3;
    #pragma unroll
    for (int nt = 0; nt < 4; ++nt) {
        const int cb = nw * 32 + nt * 8 + tg * 2;
        float2 b = *(const float2*)(bias + cb);
        #pragma unroll
        for (int mm = 0; mm < 2; ++mm) {
            const int r0 = mw * 32 + mm * 16 + qd;
            float v0 = acc[mm][nt][0] + b.x, v1 = acc[mm][nt][1] + b.y;
            float v2 = acc[mm][nt][2] + b.x, v3 = acc[mm][nt][3] + b.y;
            if (relu) {
                v0 = fmaxf(v0, 0.f); v1 = fmaxf(v1, 0.f);
                v2 = fmaxf(v2, 0.f); v3 = fmaxf(v3, 0.f);
            }
            dst[r0 * STRA + (cb >> 1)]       = pk(v0, v1);
            dst[(r0 + 8) * STRA + (cb >> 1)] = pk(v2, v3);
        }
    }
}

// epilogue -> fp32 A (col-major) in place: A[c][t] += acc + bias
__device__ __forceinline__ void epi32A(float (&acc)[2][4][4], float* __restrict__ A,
                                       const float* __restrict__ bias, int tid)
{
    const int lane = tid & 31, wid = tid >> 5;
    const int mw = wid & 1, nw = wid >> 1;
    const int qd = lane >> 2, tg = lane & 3;
    #pragma unroll
    for (int nt = 0; nt < 4; ++nt) {
        const int cb = nw * 32 + nt * 8 + tg * 2;
        float2 b = *(const float2*)(bias + cb);
        #pragma unroll
        for (int mm = 0; mm < 2; ++mm) {
            const int r0 = mw * 32 + mm * 16 + qd;
            A[cb * ASTR + r0]           += acc[mm][nt][0] + b.x;
            A[(cb + 1) * ASTR + r0]     += acc[mm][nt][1] + b.y;
            A[cb * ASTR + r0 + 8]       += acc[mm][nt][2] + b.x;
            A[(cb + 1) * ASTR + r0 + 8] += acc[mm][nt][3] + b.y;
        }
    }
}

// LayerNorm: conflict-free mapping t=tid&63, q=tid>>6; smem 2-stage reduce.
// Includes one internal __syncthreads between partial write and reduce.
__device__ __forceinline__ void lnA(const float* __restrict__ A, unsigned* __restrict__ X,
                                    const float* __restrict__ g, const float* __restrict__ be,
                                    float* __restrict__ red, int tid)
{
    const int t = tid & 63, q = tid >> 6;
    const float* Ac = A + q * 32 * ASTR + t;
    float v[32];
    float s = 0.f, sq = 0.f;
    #pragma unroll
    for (int i = 0; i < 32; ++i) {
        v[i] = Ac[i * ASTR];            // banks: t distinct across lanes -> conflict-free
        s += v[i]; sq += v[i] * v[i];
    }
    red[q * 64 + t]       = s;
    red[256 + q * 64 + t] = sq;
    __syncthreads();
    float S = 0.f, SQ = 0.f;
    #pragma unroll
    for (int k = 0; k < 4; ++k) {
        S  += red[k * 64 + t];
        SQ += red[256 + k * 64 + t];
    }
    float m = S * (1.f / CC);
    float rs = rsqrtf(SQ * (1.f / CC) - m * m + 1e-5f);

    const float2* g2 = (const float2*)(g + q * 32);
    const float2* b2 = (const float2*)(be + q * 32);
    uint4* o = (uint4*)(X + t * STRA + q * 16);
    #pragma unroll
    for (int c4 = 0; c4 < 4; ++c4) {
        uint4 w;
        unsigned r[4];
        #pragma unroll
        for (int k = 0; k < 4; ++k) {
            int i = c4 * 4 + k;
            float2 gg = g2[i], bb = b2[i];
            r[k] = pk((v[2*i] - m) * rs * gg.x + bb.x,
                      (v[2*i+1] - m) * rs * gg.y + bb.y);
        }
        w.x = r[0]; w.y = r[1]; w.z = r[2]; w.w = r[3];
        o[c4] = w;                       // STS.128, phase-conflict-free
    }
}

#define ZACC(a) { _Pragma("unroll") for (int _m = 0; _m < 2; ++_m) _Pragma("unroll") for (int _n = 0; _n < 4; ++_n) { a[_m][_n][0]=0.f; a[_m][_n][1]=0.f; a[_m][_n][2]=0.f; a[_m][_n][3]=0.f; } }

__global__ void __launch_bounds__(NTHREADS, 2)
polar_attention_kernel(
    const float* __restrict__ x,   const float* __restrict__ polar,
    const float* __restrict__ bq,  const float* __restrict__ bk,
    const float* __restrict__ bv,  const float* __restrict__ Wp,
    const float* __restrict__ bpv, const float* __restrict__ bo,
    const float* __restrict__ g1,  const float* __restrict__ be1,
    const float* __restrict__ g2,  const float* __restrict__ be2,
    const float* __restrict__ bf1, const float* __restrict__ bf2,
    float* __restrict__ out)
{
    extern __shared__ float sm[];
    unsigned* smu = (unsigned*)sm;
    float*    A   = sm + OFF_A;
    unsigned* X16 = smu + OFF_X;
    unsigned* Q16 = smu + OFF_Q;
    unsigned* K16 = smu + OFF_K;
    unsigned* V16 = smu + OFF_V;
    float*    pol = sm + OFF_POL;
    float*    red = sm + OFF_RED;

    const int tid = threadIdx.x;
    const int n0  = blockIdx.x * TOK;
    const int b   = n0 / SS;
    const int s0  = n0 % SS;

    const float* xg = x + (size_t)(b * CC) * SS + s0;
    const float* pg = polar + (size_t)(b * PCH) * SS + s0;

    // ---- load x tile (col-major A) + polar ----
    #pragma unroll
    for (int idx = tid; idx < 2048; idx += NTHREADS) {
        int c = idx >> 4, t4 = (idx & 15) * 4;
        *(float4*)(A + c * ASTR + t4) = *(const float4*)(xg + (size_t)c * SS + t4);
    }
    for (int i = tid; i < 96; i += NTHREADS) {
        int p = i >> 4, t4 = (i & 15) * 4;
        *(float4*)(pol + p * 64 + t4) = *(const float4*)(pg + (size_t)p * SS + t4);
    }
    __syncthreads();

    // ---- x_with_polar = x + polar @ Wp + bp (A in place) ----
    #pragma unroll
    for (int idx = tid; idx < 2048; idx += NTHREADS) {
        int c = idx >> 4, t4 = (idx & 15) * 4;
        float4 v = *(const float4*)(A + c * ASTR + t4);
        #pragma unroll
        for (int p = 0; p < PCH; ++p) {
            float w = Wp[p * 128 + c];
            float4 pv = *(const float4*)(pol + p * 64 + t4);
            v.x = fmaf(pv.x, w, v.x); v.y = fmaf(pv.y, w, v.y);
            v.z = fmaf(pv.z, w, v.z); v.w = fmaf(pv.w, w, v.w);
        }
        float bb = bpv[c];
        v.x += bb; v.y += bb; v.z += bb; v.w += bb;
        *(float4*)(A + c * ASTR + t4) = v;
    }
    __syncthreads();

    // ---- LN1 -> X16 ----
    lnA(A, X16, g1, be1, red, tid);
    __syncthreads();

    // ---- Q,K,V ----
    float acc[2][4][4];
    ZACC(acc); gemm_f(g_wfrag,          X16, acc, tid); epi16(acc, Q16, bq, false, tid);
    ZACC(acc); gemm_f(g_wfrag + 8192,   X16, acc, tid); epi16(acc, K16, bk, false, tid);
    ZACC(acc); gemm_f(g_wfrag + 16384,  X16, acc, tid); epi16(acc, V16, bv, false, tid);
    __syncthreads();

    // ---- per-token cross-head attention: 4 thr/token, 2 heads each, uint4 reads ----
    {
        const int t = tid >> 2;
        const int h0q = (tid & 3) * 2;
        const uint4* Qv = (const uint4*)(Q16 + t * STRA);
        const uint4* Kv = (const uint4*)(K16 + t * STRA);
        const uint4* Vv = (const uint4*)(V16 + t * STRA);

        float q[2][16];
        up8(q[0],     Qv[h0q * 2]);
        up8(q[0] + 8, Qv[h0q * 2 + 1]);
        up8(q[1],     Qv[h0q * 2 + 2]);
        up8(q[1] + 8, Qv[h0q * 2 + 3]);

        float sc[2][NHEAD];
        #pragma unroll
        for (int g = 0; g < NHEAD; ++g) {
            float kv[16];
            up8(kv,     Kv[g * 2]);
            up8(kv + 8, Kv[g * 2 + 1]);
            #pragma unroll
            for (int hh = 0; hh < 2; ++hh) {
                float s = 0.f;
                #pragma unroll
                for (int i = 0; i < 16; ++i) s = fmaf(q[hh][i], kv[i], s);
                sc[hh][g] = s * 0.25f;
            }
        }
        #pragma unroll
        for (int hh = 0; hh < 2; ++hh) {
            float mx = sc[hh][0];
            #pragma unroll
            for (int g = 1; g < NHEAD; ++g) mx = fmaxf(mx, sc[hh][g]);
            float sum = 0.f;
            #pragma unroll
            for (int g = 0; g < NHEAD; ++g) { float e = __expf(sc[hh][g] - mx); sc[hh][g] = e; sum += e; }
            float inv = 1.f / sum;
            #pragma unroll
            for (int g = 0; g < NHEAD; ++g) sc[hh][g] *= inv;
        }
        float att[2][16];
        #pragma unroll
        for (int hh = 0; hh < 2; ++hh)
            #pragma unroll
            for (int i = 0; i < 16; ++i) att[hh][i] = 0.f;
        #pragma unroll
        for (int g = 0; g < NHEAD; ++g) {
            float vv[16];
            up8(vv,     Vv[g * 2]);
            up8(vv + 8, Vv[g * 2 + 1]);
            #pragma unroll
            for (int hh = 0; hh < 2; ++hh) {
                float w = sc[hh][g];
                #pragma unroll
                for (int i = 0; i < 16; ++i)
                    att[hh][i] = fmaf(w, vv[i], att[hh][i]);
            }
        }
        #pragma unroll
        for (int hh = 0; hh < 2; ++hh)
            #pragma unroll
            for (int i = 0; i < 8; ++i)
                X16[t * STRA + (h0q + hh) * 8 + i] = pk(att[hh][2*i], att[hh][2*i+1]);
    }
    __syncthreads();

    // ---- out1 = attended @ Wo + bo + residual1 (A in place) ----
    ZACC(acc); gemm_f(g_wfrag + 24576, X16, acc, tid); epi32A(acc, A, bo, tid);
    __syncthreads();

    // ---- LN2 -> X16 ----
    lnA(A, X16, g2, be2, red, tid);
    __syncthreads();

    // ---- FFN: acc2 held; relu double-buffered (one sync per chunk) ----
    float acc2[2][4][4];
    ZACC(acc2);
    #pragma unroll 1
    for (int jb = 0; jb < 4; ++jb) {
        unsigned* X2 = smu + ((jb & 1) ? OFF_X2B : OFF_X2A);
        float h1[2][4][4];
        ZACC(h1);
        gemm_f(g_wfrag + (4 + jb) * 8192, X16, h1, tid);
        epi16(h1, X2, bf1 + jb * 128, true, tid);
        __syncthreads();     // X2 visible; alternating buffers make this the only sync needed
        gemm_f(g_wfrag + (8 + jb) * 8192, X2, acc2, tid);
    }
    __syncthreads();
    epi32A(acc2, A, bf2, tid);
    __syncthreads();

    // ---- coalesced global store ----
    float* og = out + (size_t)(b * CC) * SS + s0;
    #pragma unroll
    for (int idx = tid; idx < 2048; idx += NTHREADS) {
        int c = idx >> 4, t4 = (idx & 15) * 4;
        *(float4*)(og + (size_t)c * SS + t4) = *(const float4*)(A + c * ASTR + t4);
    }
}

extern "C" void kernel_launch(void* const* d_in, const int* in_sizes, int n_in,
                              void* d_out, int out_size)
{
    (void)in_sizes; (void)n_in; (void)out_size;
    cudaFuncSetAttribute(polar_attention_kernel,
                         cudaFuncAttributeMaxDynamicSharedMemorySize, SMEM_BYTES);

    const float* x     = (const float*)d_in[0];
    const float* polar = (const float*)d_in[1];
    const float* Wq    = (const float*)d_in[2];
    const float* bq    = (const float*)d_in[3];
    const float* Wk    = (const float*)d_in[4];
    const float* bk    = (const float*)d_in[5];
    const float* Wv    = (const float*)d_in[6];
    const float* bv    = (const float*)d_in[7];
    const float* Wp    = (const float*)d_in[8];
    const float* bp    = (const float*)d_in[9];
    const float* Wo    = (const float*)d_in[10];
    const float* bo    = (const float*)d_in[11];
    const float* g1    = (const float*)d_in[12];
    const float* be1   = (const float*)d_in[13];
    const float* g2    = (const float*)d_in[14];
    const float* be2   = (const float*)d_in[15];
    const float* W1    = (const float*)d_in[16];
    const float* bf1   = (const float*)d_in[17];
    const float* W2    = (const float*)d_in[18];
    const float* bf2   = (const float*)d_in[19];
    float* out = (float*)d_out;

    convert_weights<<<384, NTHREADS>>>(Wq, Wk, Wv, Wo, W1, W2);

    dim3 grid(NTOK / TOK);   // 4096 CTAs
    polar_attention_kernel<<<grid, NTHREADS, SMEM_BYTES>>>(
        x, polar, bq, bk, bv, Wp, bp, bo, g1, be1, g2, be2, bf1, bf2, out);
}

// round 13
// speedup vs baseline: 1.5321x; 1.0167x over previous
#include <cuda_runtime.h>
#include <cuda_fp16.h>

#define CC   128
#define PCH  6
#define SS   131072
#define NTOK 262144
#define TOK  64
#define NTHREADS 256
#define NHEAD 8

#define STRA 68      // fp16 activation row stride (u32 words)
#define ASTR 68      // fp32 residual A column stride: A[c][t]

// ---- shared memory layout (32-bit word offsets) ----
#define OFF_A    0                       // fp32 A [128][68] col-major
#define OFF_X    (128*ASTR)              // 8704
#define OFF_Q    (OFF_X + 64*STRA)       // 13056
#define OFF_K    (OFF_Q + 64*STRA)       // 17408
#define OFF_V    (OFF_K + 64*STRA)       // 21760
#define OFF_X2A  OFF_Q                   // FFN relu buf A (Q dead in FFN)
#define OFF_X2B  OFF_K                   // FFN relu buf B (K dead in FFN)
#define OFF_POL  (OFF_V + 64*STRA)       // 26112
#define OFF_RED  (OFF_POL + PCH*64)      // 26496: LN reduction scratch
#define SMEM_WORDS (OFF_RED + 512)       // 27008
#define SMEM_BYTES (SMEM_WORDS*4)        // 108032 B -> 2 CTAs/SM

// 12 fragment blocks of 128x128: Wq,Wk,Wv,Wo, W1 n-chunks x4, W2 k-chunks x4
__device__ unsigned g_wfrag[12 * 8192];

// ---- fp16 helpers ----
__device__ __forceinline__ unsigned pk(float lo, float hi) {
    __half2 h = __floats2half2_rn(lo, hi);
    return *reinterpret_cast<unsigned*>(&h);
}
__device__ __forceinline__ float2 up(unsigned w) {
    __half2 h = *reinterpret_cast<__half2*>(&w);
    return __half22float2(h);
}
__device__ __forceinline__ void up8(float* f, uint4 u) {
    float2 a = up(u.x), b = up(u.y), c = up(u.z), d = up(u.w);
    f[0] = a.x; f[1] = a.y; f[2] = b.x; f[3] = b.y;
    f[4] = c.x; f[5] = c.y; f[6] = d.x; f[7] = d.y;
}
__device__ __forceinline__ void mma16(float (&d)[4],
    unsigned a0, unsigned a1, unsigned a2, unsigned a3, unsigned b0, unsigned b1)
{
    asm("mma.sync.aligned.m16n8k16.row.col.f32.f16.f16.f32 "
        "{%0,%1,%2,%3}, {%4,%5,%6,%7}, {%8,%9}, {%0,%1,%2,%3};"
        : "+f"(d[0]), "+f"(d[1]), "+f"(d[2]), "+f"(d[3])
        : "r"(a0), "r"(a1), "r"(a2), "r"(a3), "r"(b0), "r"(b1));
}
__device__ __forceinline__ void ldsm4(unsigned (&a)[4], unsigned addr) {
    asm volatile("ldmatrix.sync.aligned.m8n8.x4.shared.b16 {%0,%1,%2,%3}, [%4];"
        : "=r"(a[0]), "=r"(a[1]), "=r"(a[2]), "=r"(a[3]) : "r"(addr));
}

// ---- weight conversion kernel: fp32 row-major -> fp16 fragment-major ----
__global__ void convert_weights(const float* __restrict__ Wq, const float* __restrict__ Wk,
                                const float* __restrict__ Wv, const float* __restrict__ Wo,
                                const float* __restrict__ W1, const float* __restrict__ W2)
{
    int gid = blockIdx.x * blockDim.x + threadIdx.x;
    int blk = gid >> 13;
    int w   = gid & 8191;
    int q4   = w & 3;
    int lane = (w >> 2) & 31;
    int h    = (w >> 7) & 1;
    int nw   = (w >> 8) & 3;
    int ks   = w >> 10;
    int j    = q4 & 1;
    int nt   = h * 2 + (q4 >> 1);
    int qd = lane >> 2, tg = lane & 3;
    int k = ks * 16 + tg * 2 + j * 8;
    int n = nw * 32 + nt * 8 + qd;

    const float* W; int ld = 128, k0 = 0, n0 = 0;
    if      (blk == 0) W = Wq;
    else if (blk == 1) W = Wk;
    else if (blk == 2) W = Wv;
    else if (blk == 3) W = Wo;
    else if (blk < 8)  { W = W1; ld = 512; n0 = (blk - 4) * 128; }
    else               { W = W2; k0 = (blk - 8) * 128; }

    const float* p = W + (size_t)(k0 + k) * ld + n0 + n;
    g_wfrag[gid] = pk(p[0], p[ld]);
}

// B pipeline: P[0],P[1] = stage ks (lo,hi); P[2],P[3] = stage ks+1
__device__ __forceinline__ void bpinit(uint4 (&P)[4], const unsigned* __restrict__ Wf, int tid) {
    const uint4* bp = (const uint4*)Wf + ((tid >> 6)) * 64 + (tid & 31);
    P[0] = bp[0]; P[1] = bp[32]; P[2] = bp[256]; P[3] = bp[256 + 32];
}

// ---- GEMM: acc[2][4][4] += X[64x128 fp16] @ Wf; depth-2 B pipeline,
//      tail prefetches Wfn's stages 0,1 into P for the next GEMM ----
__device__ __forceinline__ void gemm_pf(
    const unsigned* __restrict__ Wf, const unsigned* __restrict__ Wfn,
    const unsigned* __restrict__ Xs,
    float (&acc)[2][4][4], int tid, uint4 (&P)[4])
{
    const int lane = tid & 31, wid = tid >> 5;
    const int mw = wid & 1, nw = wid >> 1;

    unsigned abase;
    {
        const unsigned* p = Xs + (mw * 32 + (lane & 15)) * STRA;
        abase = (unsigned)__cvta_generic_to_shared(p) + ((lane >> 4) << 4);
    }
    const uint4* bp  = (const uint4*)Wf  + nw * 64 + lane;
    const uint4* bpn = (const uint4*)Wfn + nw * 64 + lane;

    unsigned aC[2][4], aN[2][4];
    ldsm4(aC[0], abase);
    ldsm4(aC[1], abase + 16 * STRA * 4);

    #pragma unroll
    for (int ks = 0; ks < 8; ++ks) {
        // prefetch ks+2 (or next GEMM's stage ks-6) — issued before MMAs
        uint4 f0, f1;
        if (ks < 6) { f0 = bp[(ks + 2) * 256];  f1 = bp[(ks + 2) * 256 + 32]; }
        else        { f0 = bpn[(ks - 6) * 256]; f1 = bpn[(ks - 6) * 256 + 32]; }
        if (ks < 7) {
            unsigned an = abase + (ks + 1) * 32;
            ldsm4(aN[0], an);
            ldsm4(aN[1], an + 16 * STRA * 4);
        }
        #pragma unroll
        for (int mm = 0; mm < 2; ++mm) {
            mma16(acc[mm][0], aC[mm][0], aC[mm][1], aC[mm][2], aC[mm][3], P[0].x, P[0].y);
            mma16(acc[mm][1], aC[mm][0], aC[mm][1], aC[mm][2], aC[mm][3], P[0].z, P[0].w);
            mma16(acc[mm][2], aC[mm][0], aC[mm][1], aC[mm][2], aC[mm][3], P[1].x, P[1].y);
            mma16(acc[mm][3], aC[mm][0], aC[mm][1], aC[mm][2], aC[mm][3], P[1].z, P[1].w);
        }
        P[0] = P[2]; P[1] = P[3]; P[2] = f0; P[3] = f1;
        #pragma unroll
        for (int mm = 0; mm < 2; ++mm)
            #pragma unroll
            for (int r = 0; r < 4; ++r) aC[mm][r] = aN[mm][r];
    }
}

// epilogue -> fp16 activation buffer (+bias from gmem, optional relu)
__device__ __forceinline__ void epi16(float (&acc)[2][4][4], unsigned* __restrict__ dst,
                                      const float* __restrict__ bias, bool relu, int tid)
{
    const int lane = tid & 31, wid = tid >> 5;
    const int mw = wid & 1, nw = wid >> 1;
    const int qd = lane >> 2, tg = lane & 3;
    #pragma unroll
    for (int nt = 0; nt < 4; ++nt) {
        const int cb = nw * 32 + nt * 8 + tg * 2;
        float2 b = *(const float2*)(bias + cb);
        #pragma unroll
        for (int mm = 0; mm < 2; ++mm) {
            const int r0 = mw * 32 + mm * 16 + qd;
            float v0 = acc[mm][nt][0] + b.x, v1 = acc[mm][nt][1] + b.y;
            float v2 = acc[mm][nt][2] + b.x, v3 = acc[mm][nt][3] + b.y;
            if (relu) {
                v0 = fmaxf(v0, 0.f); v1 = fmaxf(v1, 0.f);
                v2 = fmaxf(v2, 0.f); v3 = fmaxf(v3, 0.f);
            }
            dst[r0 * STRA + (cb >> 1)]       = pk(v0, v1);
            dst[(r0 + 8) * STRA + (cb >> 1)] = pk(v2, v3);
        }
    }
}

// epilogue -> fp32 A (col-major) in place: A[c][t] += acc + bias
__device__ __forceinline__ void epi32A(float (&acc)[2][4][4], float* __restrict__ A,
                                       const float* __restrict__ bias, int tid)
{
    const int lane = tid & 31, wid = tid >> 5;
    const int mw = wid & 1, nw = wid >> 1;
    const int qd = lane >> 2, tg = lane & 3;
    #pragma unroll
    for (int nt = 0; nt < 4; ++nt) {
        const int cb = nw * 32 + nt * 8 + tg * 2;
        float2 b = *(const float2*)(bias + cb);
        #pragma unroll
        for (int mm = 0; mm < 2; ++mm) {
            const int r0 = mw * 32 + mm * 16 + qd;
            A[cb * ASTR + r0]           += acc[mm][nt][0] + b.x;
            A[(cb + 1) * ASTR + r0]     += acc[mm][nt][1] + b.y;
            A[cb * ASTR + r0 + 8]       += acc[mm][nt][2] + b.x;
            A[(cb + 1) * ASTR + r0 + 8] += acc[mm][nt][3] + b.y;
        }
    }
}

// LayerNorm: conflict-free mapping t=tid&63, q=tid>>6; smem 2-stage reduce.
__device__ __forceinline__ void lnA(const float* __restrict__ A, unsigned* __restrict__ X,
                                    const float* __restrict__ g, const float* __restrict__ be,
                                    float* __restrict__ red, int tid)
{
    const int t = tid & 63, q = tid >> 6;
    const float* Ac = A + q * 32 * ASTR + t;
    float v[32];
    float s = 0.f, sq = 0.f;
    #pragma unroll
    for (int i = 0; i < 32; ++i) {
        v[i] = Ac[i * ASTR];
        s += v[i]; sq += v[i] * v[i];
    }
    red[q * 64 + t]       = s;
    red[256 + q * 64 + t] = sq;
    __syncthreads();
    float S = 0.f, SQ = 0.f;
    #pragma unroll
    for (int k = 0; k < 4; ++k) {
        S  += red[k * 64 + t];
        SQ += red[256 + k * 64 + t];
    }
    float m = S * (1.f / CC);
    float rs = rsqrtf(SQ * (1.f / CC) - m * m + 1e-5f);

    const float2* g2 = (const float2*)(g + q * 32);
    const float2* b2 = (const float2*)(be + q * 32);
    uint4* o = (uint4*)(X + t * STRA + q * 16);
    #pragma unroll
    for (int c4 = 0; c4 < 4; ++c4) {
        uint4 w;
        unsigned r[4];
        #pragma unroll
        for (int k = 0; k < 4; ++k) {
            int i = c4 * 4 + k;
            float2 gg = g2[i], bb = b2[i];
            r[k] = pk((v[2*i] - m) * rs * gg.x + bb.x,
                      (v[2*i+1] - m) * rs * gg.y + bb.y);
        }
        w.x = r[0]; w.y = r[1]; w.z = r[2]; w.w = r[3];
        o[c4] = w;
    }
}

#define ZACC(a) { _Pragma("unroll") for (int _m = 0; _m < 2; ++_m) _Pragma("unroll") for (int _n = 0; _n < 4; ++_n) { a[_m][_n][0]=0.f; a[_m][_n][1]=0.f; a[_m][_n][2]=0.f; a[_m][_n][3]=0.f; } }

__global__ void __launch_bounds__(NTHREADS, 2)
polar_attention_kernel(
    const float* __restrict__ x,   const float* __restrict__ polar,
    const float* __restrict__ bq,  const float* __restrict__ bk,
    const float* __restrict__ bv,  const float* __restrict__ Wp,
    const float* __restrict__ bpv, const float* __restrict__ bo,
    const float* __restrict__ g1,  const float* __restrict__ be1,
    const float* __restrict__ g2,  const float* __restrict__ be2,
    const float* __restrict__ bf1, const float* __restrict__ bf2,
    float* __restrict__ out)
{
    extern __shared__ float sm[];
    unsigned* smu = (unsigned*)sm;
    float*    A   = sm + OFF_A;
    unsigned* X16 = smu + OFF_X;
    unsigned* Q16 = smu + OFF_Q;
    unsigned* K16 = smu + OFF_K;
    unsigned* V16 = smu + OFF_V;
    float*    pol = sm + OFF_POL;
    float*    red = sm + OFF_RED;

    const int tid = threadIdx.x;
    const int n0  = blockIdx.x * TOK;
    const int b   = n0 / SS;
    const int s0  = n0 % SS;

    const float* xg = x + (size_t)(b * CC) * SS + s0;
    const float* pg = polar + (size_t)(b * PCH) * SS + s0;

    // prime the B pipeline for Wq immediately (hidden under tile load + LN1)
    uint4 P[4];
    bpinit(P, g_wfrag, tid);

    // ---- load x tile (col-major A) + polar ----
    #pragma unroll
    for (int idx = tid; idx < 2048; idx += NTHREADS) {
        int c = idx >> 4, t4 = (idx & 15) * 4;
        *(float4*)(A + c * ASTR + t4) = *(const float4*)(xg + (size_t)c * SS + t4);
    }
    for (int i = tid; i < 96; i += NTHREADS) {
        int p = i >> 4, t4 = (i & 15) * 4;
        *(float4*)(pol + p * 64 + t4) = *(const float4*)(pg + (size_t)p * SS + t4);
    }
    __syncthreads();

    // ---- x_with_polar = x + polar @ Wp + bp (A in place) ----
    #pragma unroll
    for (int idx = tid; idx < 2048; idx += NTHREADS) {
        int c = idx >> 4, t4 = (idx & 15) * 4;
        float4 v = *(const float4*)(A + c * ASTR + t4);
        #pragma unroll
        for (int p = 0; p < PCH; ++p) {
            float w = Wp[p * 128 + c];
            float4 pv = *(const float4*)(pol + p * 64 + t4);
            v.x = fmaf(pv.x, w, v.x); v.y = fmaf(pv.y, w, v.y);
            v.z = fmaf(pv.z, w, v.z); v.w = fmaf(pv.w, w, v.w);
        }
        float bb = bpv[c];
        v.x += bb; v.y += bb; v.z += bb; v.w += bb;
        *(float4*)(A + c * ASTR + t4) = v;
    }
    __syncthreads();

    // ---- LN1 -> X16 ----
    lnA(A, X16, g1, be1, red, tid);
    __syncthreads();

    // ---- Q,K,V (chained B pipeline) ----
    float acc[2][4][4];
    ZACC(acc); gemm_pf(g_wfrag,         g_wfrag + 8192,  X16, acc, tid, P); epi16(acc, Q16, bq, false, tid);
    ZACC(acc); gemm_pf(g_wfrag + 8192,  g_wfrag + 16384, X16, acc, tid, P); epi16(acc, K16, bk, false, tid);
    ZACC(acc); gemm_pf(g_wfrag + 16384, g_wfrag + 16384, X16, acc, tid, P); epi16(acc, V16, bv, false, tid);
    __syncthreads();

    // ---- per-token cross-head attention: 4 thr/token, 2 heads each, uint4 reads ----
    {
        const int t = tid >> 2;
        const int h0q = (tid & 3) * 2;
        const uint4* Qv = (const uint4*)(Q16 + t * STRA);
        const uint4* Kv = (const uint4*)(K16 + t * STRA);
        const uint4* Vv = (const uint4*)(V16 + t * STRA);

        float q[2][16];
        up8(q[0],     Qv[h0q * 2]);
        up8(q[0] + 8, Qv[h0q * 2 + 1]);
        up8(q[1],     Qv[h0q * 2 + 2]);
        up8(q[1] + 8, Qv[h0q * 2 + 3]);

        float sc[2][NHEAD];
        #pragma unroll
        for (int g = 0; g < NHEAD; ++g) {
            float kv[16];
            up8(kv,     Kv[g * 2]);
            up8(kv + 8, Kv[g * 2 + 1]);
            #pragma unroll
            for (int hh = 0; hh < 2; ++hh) {
                float s = 0.f;
                #pragma unroll
                for (int i = 0; i < 16; ++i) s = fmaf(q[hh][i], kv[i], s);
                sc[hh][g] = s * 0.25f;
            }
        }
        #pragma unroll
        for (int hh = 0; hh < 2; ++hh) {
            float mx = sc[hh][0];
            #pragma unroll
            for (int g = 1; g < NHEAD; ++g) mx = fmaxf(mx, sc[hh][g]);
            float sum = 0.f;
            #pragma unroll
            for (int g = 0; g < NHEAD; ++g) { float e = __expf(sc[hh][g] - mx); sc[hh][g] = e; sum += e; }
            float inv = 1.f / sum;
            #pragma unroll
            for (int g = 0; g < NHEAD; ++g) sc[hh][g] *= inv;
        }
        float att[2][16];
        #pragma unroll
        for (int hh = 0; hh < 2; ++hh)
            #pragma unroll
            for (int i = 0; i < 16; ++i) att[hh][i] = 0.f;
        #pragma unroll
        for (int g = 0; g < NHEAD; ++g) {
            float vv[16];
            up8(vv,     Vv[g * 2]);
            up8(vv + 8, Vv[g * 2 + 1]);
            #pragma unroll
            for (int hh = 0; hh < 2; ++hh) {
                float w = sc[hh][g];
                #pragma unroll
                for (int i = 0; i < 16; ++i)
                    att[hh][i] = fmaf(w, vv[i], att[hh][i]);
            }
        }
        #pragma unroll
        for (int hh = 0; hh < 2; ++hh)
            #pragma unroll
            for (int i = 0; i < 8; ++i)
                X16[t * STRA + (h0q + hh) * 8 + i] = pk(att[hh][2*i], att[hh][2*i+1]);
    }
    // re-prime B pipeline for Wo (overlaps the sync below)
    bpinit(P, g_wfrag + 24576, tid);
    __syncthreads();

    // ---- out1 = attended @ Wo + bo + residual1 (A in place); tail prefetches W1[0] ----
    ZACC(acc); gemm_pf(g_wfrag + 24576, g_wfrag + 4 * 8192, X16, acc, tid, P);
    epi32A(acc, A, bo, tid);
    __syncthreads();

    // ---- LN2 -> X16 ----
    lnA(A, X16, g2, be2, red, tid);
    __syncthreads();

    // ---- FFN: acc2 held; relu double-buffered; B chained through all 8 GEMMs ----
    float acc2[2][4][4];
    ZACC(acc2);
    #pragma unroll 1
    for (int jb = 0; jb < 4; ++jb) {
        unsigned* X2 = smu + ((jb & 1) ? OFF_X2B : OFF_X2A);
        float h1[2][4][4];
        ZACC(h1);
        gemm_pf(g_wfrag + (4 + jb) * 8192, g_wfrag + (8 + jb) * 8192, X16, h1, tid, P);
        epi16(h1, X2, bf1 + jb * 128, true, tid);
        __syncthreads();
        const unsigned* nxt = (jb < 3) ? g_wfrag + (5 + jb) * 8192
                                       : g_wfrag + (8 + jb) * 8192;   // dummy on last
        gemm_pf(g_wfrag + (8 + jb) * 8192, nxt, X2, acc2, tid, P);
    }
    __syncthreads();
    epi32A(acc2, A, bf2, tid);
    __syncthreads();

    // ---- coalesced global store ----
    float* og = out + (size_t)(b * CC) * SS + s0;
    #pragma unroll
    for (int idx = tid; idx < 2048; idx += NTHREADS) {
        int c = idx >> 4, t4 = (idx & 15) * 4;
        *(float4*)(og + (size_t)c * SS + t4) = *(const float4*)(A + c * ASTR + t4);
    }
}

extern "C" void kernel_launch(void* const* d_in, const int* in_sizes, int n_in,
                              void* d_out, int out_size)
{
    (void)in_sizes; (void)n_in; (void)out_size;
    cudaFuncSetAttribute(polar_attention_kernel,
                         cudaFuncAttributeMaxDynamicSharedMemorySize, SMEM_BYTES);

    const float* x     = (const float*)d_in[0];
    const float* polar = (const float*)d_in[1];
    const float* Wq    = (const float*)d_in[2];
    const float* bq    = (const float*)d_in[3];
    const float* Wk    = (const float*)d_in[4];
    const float* bk    = (const float*)d_in[5];
    const float* Wv    = (const float*)d_in[6];
    const float* bv    = (const float*)d_in[7];
    const float* Wp    = (const float*)d_in[8];
    const float* bp    = (const float*)d_in[9];
    const float* Wo    = (const float*)d_in[10];
    const float* bo    = (const float*)d_in[11];
    const float* g1    = (const float*)d_in[12];
    const float* be1   = (const float*)d_in[13];
    const float* g2    = (const float*)d_in[14];
    const float* be2   = (const float*)d_in[15];
    const float* W1    = (const float*)d_in[16];
    const float* bf1   = (const float*)d_in[17];
    const float* W2    = (const float*)d_in[18];
    const float* bf2   = (const float*)d_in[19];
    float* out = (float*)d_out;

    convert_weights<<<384, NTHREADS>>>(Wq, Wk, Wv, Wo, W1, W2);

    dim3 grid(NTOK / TOK);   // 4096 CTAs
    polar_attention_kernel<<<grid, NTHREADS, SMEM_BYTES>>>(
        x, polar, bq, bk, bv, Wp, bp, bo, g1, be1, g2, be2, bf1, bf2, out);
}